// round 4
// baseline (speedup 1.0000x reference)
#include <cuda_runtime.h>
#include <math.h>

#define Dd 64
#define Nn 8192
#define Mm 256
#define NH 32
#define DN     0.3535533905932738f   /* 64^-0.25 */
#define RATIO  0.0625f               /* 256^-0.5 */
#define REPS   6.25e-8f              /* RATIO * 1e-6 */
#define DIAGC  0.0625f               /* DN^2 * 0.5 */

typedef unsigned long long u64;

// ---------------- scratch (device globals; no allocation) ----------------
__device__ float    g_projT[64 * 256];                    // [d][m], pre-scaled by DN
__device__ float    g_kbuf[(size_t)NH * Nn * Mm];         // [head][n][m] : u - diag
__device__ unsigned g_kmax[NH];                           // per-head max(raw u), ordered key
__device__ float    g_kvpart[(size_t)NH * 32 * 256 * 68]; // [head][slice][m][68]
__device__ float    g_kvaug[(size_t)NH * 256 * 68];       // [head][m][0..63]=kv, [64]=knorm

// packed fp32x2 FMA (Blackwell FFMA2; ptxas never auto-fuses — PTX only)
static __device__ __forceinline__ u64 ffma2(u64 a, u64 b, u64 c) {
    u64 d;
    asm("fma.rn.f32x2 %0, %1, %2, %3;" : "=l"(d) : "l"(a), "l"(b), "l"(c));
    return d;
}
static __device__ __forceinline__ float f2lo(u64 v) { return __uint_as_float((unsigned)v); }
static __device__ __forceinline__ float f2hi(u64 v) { return __uint_as_float((unsigned)(v >> 32)); }

// order-preserving float->uint key
static __device__ __forceinline__ unsigned fkey(float f) {
    unsigned b = __float_as_uint(f);
    return (b & 0x80000000u) ? ~b : (b | 0x80000000u);
}

// branch-free exp on FMA/ALU pipes (no MUFU). Valid for x <= 0, ~2.4e-6 rel err.
static __device__ __forceinline__ float fexp(float x) {
    float t = x * 1.4426950408889634f;
    t = fmaxf(t, -125.0f);
    float r  = t + 12582912.0f;
    float fi = r - 12582912.0f;
    float f  = t - fi;
    float p = 1.3333558e-3f;
    p = fmaf(p, f, 9.6181291e-3f);
    p = fmaf(p, f, 5.5504109e-2f);
    p = fmaf(p, f, 2.4022651e-1f);
    p = fmaf(p, f, 6.9314718e-1f);
    p = fmaf(p, f, 1.0f);
    int ib = __float_as_int(r) - 0x4B400000;
    float s = __int_as_float((ib + 127) << 23);
    return p * s;
}

// ---------------- K0: scaled projT + reset kmax ----------------
__global__ void k_init(const float* __restrict__ proj)
{
    int idx = blockIdx.x * 256 + threadIdx.x;
    if (idx < 64 * 256) {
        int d = idx >> 8, m = idx & 255;
        g_projT[idx] = proj[m * 64 + d] * DN;
    }
    if (idx < NH) g_kmax[idx] = 0u;
}

// ---------------- K1: key projection -> g_kbuf (u - diag), + head max --------
// Grid (128, 32). Block 256. Tile 256(m) x 64(n), K=64. 8x8 tile/thread, FFMA2.
// smem: Ps [64][256] natural; Xs [64][128] DUPLICATED pairs (x,x) per token.
__global__ void __launch_bounds__(256, 2) k_proj_keys(const float* __restrict__ key)
{
    extern __shared__ float sm[];
    float* Ps = sm;            // [64][256]
    float* Xs = sm + 16384;    // [64][128] duplicated
    __shared__ float red[8];
    __shared__ float sq[64];

    const int t = threadIdx.x;
    const int head = blockIdx.y;
    const int n0 = blockIdx.x * 64;

    {   // stage projT (already [d][m] scaled)
        const float4* s4 = (const float4*)g_projT;
        float4* d4 = (float4*)Ps;
        #pragma unroll
        for (int r = 0; r < 16; r++) d4[t + 256 * r] = s4[t + 256 * r];
    }
    {   // stage key tile [64d][64n] duplicated
        const float* kp = key + (size_t)head * Dd * Nn;
        #pragma unroll
        for (int r = 0; r < 4; r++) {
            int e4 = t + 256 * r;
            int dd = e4 >> 4, n4 = e4 & 15;
            float4 v = *(const float4*)(kp + (size_t)dd * Nn + n0 + n4 * 4);
            float2* dst = (float2*)(Xs + dd * 128 + n4 * 8);
            dst[0] = make_float2(v.x, v.x);
            dst[1] = make_float2(v.y, v.y);
            dst[2] = make_float2(v.z, v.z);
            dst[3] = make_float2(v.w, v.w);
        }
    }
    __syncthreads();

    // per-token ||x||^2 (deterministic, tiny)
    if (t < 64) {
        float s = 0.0f;
        #pragma unroll 8
        for (int kk = 0; kk < 64; kk++) {
            float v = Xs[kk * 128 + 2 * t];
            s = fmaf(v, v, s);
        }
        sq[t] = s;
    }

    const int tm  = (t >> 3) << 3;
    const int tn4 = (t & 7) << 2;

    u64 acc2[4][8];
    #pragma unroll
    for (int i = 0; i < 4; i++)
        #pragma unroll
        for (int j = 0; j < 8; j++) acc2[i][j] = 0ull;

    #pragma unroll 4
    for (int kk = 0; kk < 64; kk++) {
        ulonglong2 A0 = *(const ulonglong2*)(Ps + kk * 256 + tm);
        ulonglong2 A1 = *(const ulonglong2*)(Ps + kk * 256 + tm + 4);
        u64 av2[4] = {A0.x, A0.y, A1.x, A1.y};
        ulonglong2 B0 = *(const ulonglong2*)(Xs + kk * 128 + 2 * tn4);
        ulonglong2 B1 = *(const ulonglong2*)(Xs + kk * 128 + 2 * tn4 + 4);
        ulonglong2 B2 = *(const ulonglong2*)(Xs + kk * 128 + 64 + 2 * tn4);
        ulonglong2 B3 = *(const ulonglong2*)(Xs + kk * 128 + 64 + 2 * tn4 + 4);
        u64 bv2[8] = {B0.x, B0.y, B1.x, B1.y, B2.x, B2.y, B3.x, B3.y};
        #pragma unroll
        for (int j = 0; j < 8; j++)
            #pragma unroll
            for (int i = 0; i < 4; i++)
                acc2[i][j] = ffma2(av2[i], bv2[j], acc2[i][j]);
    }

    // block max of raw u -> atomicMax per head
    float bm = -3.4e38f;
    #pragma unroll
    for (int i = 0; i < 4; i++)
        #pragma unroll
        for (int j = 0; j < 8; j++)
            bm = fmaxf(bm, fmaxf(f2lo(acc2[i][j]), f2hi(acc2[i][j])));
    #pragma unroll
    for (int o = 16; o; o >>= 1) bm = fmaxf(bm, __shfl_xor_sync(0xffffffffu, bm, o));
    if ((t & 31) == 0) red[t >> 5] = bm;
    __syncthreads();
    if (t == 0) {
        float m0 = red[0];
        #pragma unroll
        for (int w = 1; w < 8; w++) m0 = fmaxf(m0, red[w]);
        atomicMax(g_kmax + head, fkey(m0));
    }

    // write u - diag, layout [head][n][m]
    float* gb = g_kbuf + ((size_t)head * Nn + n0) * Mm;
    #pragma unroll
    for (int j = 0; j < 8; j++) {
        int n = (j < 4) ? (tn4 + j) : (28 + tn4 + j);
        float dg = sq[n] * DIAGC;
        *(float4*)(gb + (size_t)n * Mm + tm) =
            make_float4(f2lo(acc2[0][j])-dg, f2hi(acc2[0][j])-dg,
                        f2lo(acc2[1][j])-dg, f2hi(acc2[1][j])-dg);
        *(float4*)(gb + (size_t)n * Mm + tm + 4) =
            make_float4(f2lo(acc2[2][j])-dg, f2hi(acc2[2][j])-dg,
                        f2lo(acc2[3][j])-dg, f2hi(acc2[3][j])-dg);
    }
}

// ---------------- K2: k_phi + partial kv/knorm ----------------
// Grid (32 slices, 32 heads). Block 256. Each block: 256 tokens, 8 chunks of 32.
// Pairs along m (PHI natural pairs); Vs duplicated for broadcast operand.
__global__ void __launch_bounds__(256, 2) k_kv_accum(const float* __restrict__ value)
{
    extern __shared__ float sm[];
    float* PHIs = sm;          // [32][264]  ([n][m] padded)
    float* Vs   = sm + 8448;   // [32][136]  duplicated [n][2d]

    const int t = threadIdx.x;
    const int head = blockIdx.y;
    const int slice = blockIdx.x;
    const float kmax = [](unsigned k){
        return __uint_as_float((k & 0x80000000u) ? (k & 0x7fffffffu) : ~k);
    }(g_kmax[head]);

    const int tm = (t >> 3) << 3;   // m base (0..248)
    const int td = (t & 7) << 3;    // d base (0..56)
    const u64 ONE2 = 0x3f8000003f800000ull;

    u64 acc2[4][8];
    u64 nrm2[4];
    #pragma unroll
    for (int i = 0; i < 4; i++) {
        nrm2[i] = 0ull;
        #pragma unroll
        for (int j = 0; j < 8; j++) acc2[i][j] = 0ull;
    }

    const float* vp = value + (size_t)head * Dd * Nn;
    const float* kb = g_kbuf + ((size_t)head * Nn + (size_t)slice * 256) * Mm;

    for (int c = 0; c < 8; c++) {
        const int n0 = slice * 256 + c * 32;
        __syncthreads();
        {   // stage PHI[n][m] with exp applied
            const float4* src = (const float4*)(kb + (size_t)c * 32 * Mm);
            #pragma unroll
            for (int r = 0; r < 8; r++) {
                int e4 = t + 256 * r;
                int n = e4 >> 6, m4 = e4 & 63;
                float4 v = src[(size_t)n * 64 + m4];
                float4 p;
                p.x = RATIO * fexp(v.x - kmax) + REPS;
                p.y = RATIO * fexp(v.y - kmax) + REPS;
                p.z = RATIO * fexp(v.z - kmax) + REPS;
                p.w = RATIO * fexp(v.w - kmax) + REPS;
                *(float4*)(PHIs + n * 264 + m4 * 4) = p;
            }
        }
        {   // stage Vs[n][2d] duplicated
            #pragma unroll
            for (int r = 0; r < 8; r++) {
                int idx = t + 256 * r;
                int n = idx & 31, d = idx >> 5;
                float v = vp[(size_t)d * Nn + n0 + n];
                *(float2*)(Vs + n * 136 + 2 * d) = make_float2(v, v);
            }
        }
        __syncthreads();

        #pragma unroll 4
        for (int n = 0; n < 32; n++) {
            ulonglong2 A0 = *(const ulonglong2*)(PHIs + n * 264 + tm);
            ulonglong2 A1 = *(const ulonglong2*)(PHIs + n * 264 + tm + 4);
            u64 av2[4] = {A0.x, A0.y, A1.x, A1.y};
            ulonglong2 B0 = *(const ulonglong2*)(Vs + n * 136 + 2 * td);
            ulonglong2 B1 = *(const ulonglong2*)(Vs + n * 136 + 2 * td + 4);
            ulonglong2 B2 = *(const ulonglong2*)(Vs + n * 136 + 2 * td + 8);
            ulonglong2 B3 = *(const ulonglong2*)(Vs + n * 136 + 2 * td + 12);
            u64 bv2[8] = {B0.x, B0.y, B1.x, B1.y, B2.x, B2.y, B3.x, B3.y};
            if ((t & 7) == 0) {
                #pragma unroll
                for (int i = 0; i < 4; i++) nrm2[i] = ffma2(av2[i], ONE2, nrm2[i]);
            }
            #pragma unroll
            for (int j = 0; j < 8; j++)
                #pragma unroll
                for (int i = 0; i < 4; i++)
                    acc2[i][j] = ffma2(av2[i], bv2[j], acc2[i][j]);
        }
    }

    float* dst = g_kvpart + (size_t)(head * 32 + slice) * 17408;
    #pragma unroll
    for (int i2 = 0; i2 < 4; i2++) {
        int iL = tm + 2 * i2, iH = iL + 1;
        *(float4*)(dst + iL * 68 + td) =
            make_float4(f2lo(acc2[i2][0]), f2lo(acc2[i2][1]), f2lo(acc2[i2][2]), f2lo(acc2[i2][3]));
        *(float4*)(dst + iL * 68 + td + 4) =
            make_float4(f2lo(acc2[i2][4]), f2lo(acc2[i2][5]), f2lo(acc2[i2][6]), f2lo(acc2[i2][7]));
        *(float4*)(dst + iH * 68 + td) =
            make_float4(f2hi(acc2[i2][0]), f2hi(acc2[i2][1]), f2hi(acc2[i2][2]), f2hi(acc2[i2][3]));
        *(float4*)(dst + iH * 68 + td + 4) =
            make_float4(f2hi(acc2[i2][4]), f2hi(acc2[i2][5]), f2hi(acc2[i2][6]), f2hi(acc2[i2][7]));
        if ((t & 7) == 0) {
            dst[iL * 68 + 64] = f2lo(nrm2[i2]);
            dst[iH * 68 + 64] = f2hi(nrm2[i2]);
        }
    }
}

// ---------------- K3: reduce partials -> g_kvaug ----------------
__global__ void k_reduce()
{
    int idx = blockIdx.x * 256 + threadIdx.x;   // < 32*17408
    int h = idx / 17408;
    int j = idx - h * 17408;
    float s = 0.0f;
    if (j % 68 < 65) {
        #pragma unroll
        for (int sl = 0; sl < 32; sl++)
            s += g_kvpart[(size_t)(h * 32 + sl) * 17408 + j];
    }
    g_kvaug[idx] = s;
}

// ---------------- K4: query projection + phi + output ----------------
// Grid (128, 32). Block 256.
__global__ void __launch_bounds__(256) k_query_out(const float* __restrict__ query,
                                                   float* __restrict__ out)
{
    extern __shared__ float sm[];
    float* Ps   = sm;            // phase A: [64][256]
    float* Xs   = sm + 16384;    // phase A: [64][128] duplicated
    float* PHIs = sm;            // phase B: [256][68]  (m rows, n cols)
    float* KVs  = sm + 17408;    // phase B: [256][136] duplicated, kn at 128/129
    __shared__ float redm[32 * 64];
    __shared__ float stab[64];
    __shared__ float sq[64];

    const int t = threadIdx.x;
    const int head = blockIdx.y;
    const int n0 = blockIdx.x * 64;

    {
        const float4* s4 = (const float4*)g_projT;
        float4* d4 = (float4*)Ps;
        #pragma unroll
        for (int r = 0; r < 16; r++) d4[t + 256 * r] = s4[t + 256 * r];
    }
    {
        const float* qp = query + (size_t)head * Dd * Nn;
        #pragma unroll
        for (int r = 0; r < 4; r++) {
            int e4 = t + 256 * r;
            int dd = e4 >> 4, n4 = e4 & 15;
            float4 v = *(const float4*)(qp + (size_t)dd * Nn + n0 + n4 * 4);
            float2* dst = (float2*)(Xs + dd * 128 + n4 * 8);
            dst[0] = make_float2(v.x, v.x);
            dst[1] = make_float2(v.y, v.y);
            dst[2] = make_float2(v.z, v.z);
            dst[3] = make_float2(v.w, v.w);
        }
    }
    __syncthreads();

    if (t < 64) {
        float s = 0.0f;
        #pragma unroll 8
        for (int kk = 0; kk < 64; kk++) {
            float v = Xs[kk * 128 + 2 * t];
            s = fmaf(v, v, s);
        }
        sq[t] = s;
    }

    const int tm  = (t >> 3) << 3;
    const int tn4 = (t & 7) << 2;

    u64 acc2[4][8];
    #pragma unroll
    for (int i = 0; i < 4; i++)
        #pragma unroll
        for (int j = 0; j < 8; j++) acc2[i][j] = 0ull;

    #pragma unroll 4
    for (int kk = 0; kk < 64; kk++) {
        ulonglong2 A0 = *(const ulonglong2*)(Ps + kk * 256 + tm);
        ulonglong2 A1 = *(const ulonglong2*)(Ps + kk * 256 + tm + 4);
        u64 av2[4] = {A0.x, A0.y, A1.x, A1.y};
        ulonglong2 B0 = *(const ulonglong2*)(Xs + kk * 128 + 2 * tn4);
        ulonglong2 B1 = *(const ulonglong2*)(Xs + kk * 128 + 2 * tn4 + 4);
        ulonglong2 B2 = *(const ulonglong2*)(Xs + kk * 128 + 64 + 2 * tn4);
        ulonglong2 B3 = *(const ulonglong2*)(Xs + kk * 128 + 64 + 2 * tn4 + 4);
        u64 bv2[8] = {B0.x, B0.y, B1.x, B1.y, B2.x, B2.y, B3.x, B3.y};
        #pragma unroll
        for (int j = 0; j < 8; j++)
            #pragma unroll
            for (int i = 0; i < 4; i++)
                acc2[i][j] = ffma2(av2[i], bv2[j], acc2[i][j]);
    }

    // per-column (token) max of raw u
    #pragma unroll
    for (int j = 0; j < 8; j++) {
        int col = (j < 4) ? (tn4 + j) : (28 + tn4 + j);
        float lm = fmaxf(f2lo(acc2[0][j]), f2hi(acc2[0][j]));
        #pragma unroll
        for (int i = 1; i < 4; i++)
            lm = fmaxf(lm, fmaxf(f2lo(acc2[i][j]), f2hi(acc2[i][j])));
        redm[(t >> 3) * 64 + col] = lm;
    }
    __syncthreads();   // barrier A

    {   // stage KVs duplicated: [m][2d] + kn at [128],[129]
        const float* src = g_kvaug + (size_t)head * 17408;
        #pragma unroll
        for (int r = 0; r < 16; r++) {
            int e4 = t + 256 * r;         // < 4096
            int m = e4 >> 4, d4 = e4 & 15;
            float4 v = *(const float4*)(src + m * 68 + d4 * 4);
            float2* dst = (float2*)(KVs + m * 136 + d4 * 8);
            dst[0] = make_float2(v.x, v.x);
            dst[1] = make_float2(v.y, v.y);
            dst[2] = make_float2(v.z, v.z);
            dst[3] = make_float2(v.w, v.w);
        }
        float kn = src[t * 68 + 64];
        *(float2*)(KVs + t * 136 + 128) = make_float2(kn, kn);
    }
    if (t < 64) {
        float m0 = redm[t];
        #pragma unroll
        for (int r2 = 1; r2 < 32; r2++) m0 = fmaxf(m0, redm[r2 * 64 + t]);
        stab[t] = m0;
    }
    __syncthreads();   // barrier B

    // write PHIs[m][n]
    #pragma unroll
    for (int j = 0; j < 8; j++) {
        int col = (j < 4) ? (tn4 + j) : (28 + tn4 + j);
        float cc = -sq[col] * DIAGC - stab[col];
        #pragma unroll
        for (int i2 = 0; i2 < 4; i2++) {
            PHIs[(tm + 2*i2)     * 68 + col] = RATIO * fexp(f2lo(acc2[i2][j]) + cc) + REPS;
            PHIs[(tm + 2*i2 + 1) * 68 + col] = RATIO * fexp(f2hi(acc2[i2][j]) + cc) + REPS;
        }
    }
    __syncthreads();   // barrier C

    // phase B: out[n][d] = sum_m phi[m][n] * kv[m][d]; norm via kn
    const int qn = (t & 15) << 2;   // n offset 0..60
    const int qd = (t >> 4) << 2;   // d offset 0..60
    u64 oa2[2][4];
    u64 on2[2];
    #pragma unroll
    for (int j2 = 0; j2 < 2; j2++) {
        on2[j2] = 0ull;
        #pragma unroll
        for (int d2 = 0; d2 < 4; d2++) oa2[j2][d2] = 0ull;
    }

    #pragma unroll 4
    for (int m = 0; m < 256; m++) {
        ulonglong2 P = *(const ulonglong2*)(PHIs + m * 68 + qn);
        u64 pv2[2] = {P.x, P.y};
        ulonglong2 C0 = *(const ulonglong2*)(KVs + m * 136 + 2 * qd);
        ulonglong2 C1 = *(const ulonglong2*)(KVs + m * 136 + 2 * qd + 4);
        u64 kvd[4] = {C0.x, C0.y, C1.x, C1.y};
        u64 knd = *(const u64*)(KVs + m * 136 + 128);
        #pragma unroll
        for (int j2 = 0; j2 < 2; j2++) {
            on2[j2] = ffma2(pv2[j2], knd, on2[j2]);
            #pragma unroll
            for (int d2 = 0; d2 < 4; d2++)
                oa2[j2][d2] = ffma2(pv2[j2], kvd[d2], oa2[j2][d2]);
        }
    }

    float rn[4];
    rn[0] = 1.0f / f2lo(on2[0]);
    rn[1] = 1.0f / f2hi(on2[0]);
    rn[2] = 1.0f / f2lo(on2[1]);
    rn[3] = 1.0f / f2hi(on2[1]);

    float* op = out + (size_t)head * Dd * Nn + n0 + qn;
    #pragma unroll
    for (int d2 = 0; d2 < 4; d2++) {
        *(float4*)(op + (size_t)(qd + d2) * Nn) =
            make_float4(f2lo(oa2[0][d2]) * rn[0], f2hi(oa2[0][d2]) * rn[1],
                        f2lo(oa2[1][d2]) * rn[2], f2hi(oa2[1][d2]) * rn[3]);
    }
}

// ---------------- launch ----------------
extern "C" void kernel_launch(void* const* d_in, const int* in_sizes, int n_in,
                              void* d_out, int out_size)
{
    const float* query = (const float*)d_in[0];
    const float* key   = (const float*)d_in[1];
    const float* value = (const float*)d_in[2];
    const float* proj  = (const float*)d_in[3];
    float* out = (float*)d_out;

    cudaFuncSetAttribute(k_proj_keys, cudaFuncAttributeMaxDynamicSharedMemorySize, 98304);
    cudaFuncSetAttribute(k_kv_accum,  cudaFuncAttributeMaxDynamicSharedMemorySize, 51200);
    cudaFuncSetAttribute(k_query_out, cudaFuncAttributeMaxDynamicSharedMemorySize, 208896);

    k_init<<<64, 256>>>(proj);
    k_proj_keys<<<dim3(128, 32), 256, 98304>>>(key);
    k_kv_accum<<<dim3(32, 32), 256, 51200>>>(value);
    k_reduce<<<2176, 256>>>();
    k_query_out<<<dim3(128, 32), 256, 208896>>>(query, out);
}

// round 6
// speedup vs baseline: 1.6984x; 1.6984x over previous
#include <cuda_runtime.h>
#include <cuda_bf16.h>
#include <math.h>

#define Dd 64
#define Nn 8192
#define Mm 256
#define NH 32
#define DN     0.3535533905932738f   /* 64^-0.25 */
#define RATIO  0.0625f               /* 256^-0.5 */
#define REPS   6.25e-8f              /* RATIO * 1e-6 */
#define DIAGC  0.0625f               /* DN^2 * 0.5 */

// ---------------- scratch (device globals; no allocation) ----------------
__device__ float    g_kbuf[(size_t)NH * Nn * Mm];         // [head][n][m] : u - diag (keys)
__device__ float    g_qbuf[(size_t)NH * Nn * Mm];         // [head][n][m] : phi_q
__device__ unsigned g_kmax[NH];                           // per-head max(raw u), ordered key
__device__ float    g_kvpart[(size_t)NH * 16 * 256 * 68]; // [head][slice][m][68]
__device__ float    g_kvaug[(size_t)NH * 256 * 68];       // [head][m][0..63]=kv, [64]=knorm
__device__ __align__(16) __nv_bfloat16 g_pbh[256 * 64];   // proj*DN hi, [m][d]
__device__ __align__(16) __nv_bfloat16 g_pbl[256 * 64];   // proj*DN lo, [m][d]

// order-preserving float<->uint key
static __device__ __forceinline__ unsigned fkey(float f) {
    unsigned b = __float_as_uint(f);
    return (b & 0x80000000u) ? ~b : (b | 0x80000000u);
}
static __device__ __forceinline__ float finv(unsigned k) {
    return __uint_as_float((k & 0x80000000u) ? (k & 0x7fffffffu) : ~k);
}

// branch-free exp on FMA/ALU pipes. Valid for x <= 0, ~2.4e-6 rel err.
static __device__ __forceinline__ float fexp(float x) {
    float t = x * 1.4426950408889634f;
    t = fmaxf(t, -125.0f);
    float r  = t + 12582912.0f;
    float fi = r - 12582912.0f;
    float f  = t - fi;
    float p = 1.3333558e-3f;
    p = fmaf(p, f, 9.6181291e-3f);
    p = fmaf(p, f, 5.5504109e-2f);
    p = fmaf(p, f, 2.4022651e-1f);
    p = fmaf(p, f, 6.9314718e-1f);
    p = fmaf(p, f, 1.0f);
    int ib = __float_as_int(r) - 0x4B400000;
    float s = __int_as_float((ib + 127) << 23);
    return p * s;
}

// HMMA m16n8k16 bf16 -> fp32 accum (baseline PTX, no arch-specific target needed)
static __device__ __forceinline__ void mma16816(float c[4], const unsigned a[4],
                                                unsigned b0, unsigned b1) {
    asm volatile(
        "mma.sync.aligned.m16n8k16.row.col.f32.bf16.bf16.f32 "
        "{%0,%1,%2,%3}, {%4,%5,%6,%7}, {%8,%9}, {%0,%1,%2,%3};"
        : "+f"(c[0]), "+f"(c[1]), "+f"(c[2]), "+f"(c[3])
        : "r"(a[0]), "r"(a[1]), "r"(a[2]), "r"(a[3]), "r"(b0), "r"(b1));
}

// ---------------- K0: bf16-split scaled proj + reset kmax ----------------
__global__ void k_init(const float* __restrict__ proj)
{
    int idx = blockIdx.x * 256 + threadIdx.x;   // 64 blocks x 256
    if (idx < 256 * 64) {
        float v = proj[idx] * DN;               // [m][d] layout preserved
        __nv_bfloat16 h = __float2bfloat16(v);
        g_pbh[idx] = h;
        g_pbl[idx] = __float2bfloat16(v - __bfloat162float(h));
    }
    if (idx < NH) g_kmax[idx] = 0u;
}

// ---------------- K_proj (HMMA): u = x . P^T per 64-token block ------------
// grid (128, 32), block 256 (8 warps). Warp tile: 16 tokens x 128 features.
// smem rows padded to 144 B (72 bf16) -> conflict-free fragment loads.
#define OFF_AH   0
#define OFF_AL   9216
#define OFF_PH   18432
#define OFF_PL   55296
#define OFF_SQP  92160
#define OFF_SQ   93184
#define OFF_SMAX 93440
#define PROJ_SMEM 94208

template <bool IS_QUERY>
__global__ void __launch_bounds__(256, 2) k_proj_mma(const float* __restrict__ x)
{
    extern __shared__ char smem[];
    char* Ah = smem + OFF_AH;       // [64 tok][72 bf16]
    char* Al = smem + OFF_AL;
    char* Ph = smem + OFF_PH;       // [256 feat][72 bf16]
    char* Pl = smem + OFF_PL;
    float* sqp  = (float*)(smem + OFF_SQP);   // [64][4]
    float* sq   = (float*)(smem + OFF_SQ);    // [64]
    float* smax = (float*)(smem + OFF_SMAX);  // [2][64]

    const int t = threadIdx.x;
    const int head = blockIdx.y;
    const int n0 = blockIdx.x * 64;

    // ---- stage A: x[d][tok] -> Ah/Al[tok][d] bf16 pairs + partial sumsq ----
    {
        const int tok = t & 63, dblk = t >> 6;
        const float* xp = x + (size_t)head * Dd * Nn + n0 + tok;
        float s = 0.0f;
        #pragma unroll
        for (int i = 0; i < 8; i++) {
            int d = dblk * 16 + 2 * i;
            float v0 = xp[(size_t)d * Nn];
            float v1 = xp[(size_t)(d + 1) * Nn];
            s = fmaf(v0, v0, fmaf(v1, v1, s));
            __nv_bfloat16 h0 = __float2bfloat16(v0);
            __nv_bfloat16 h1 = __float2bfloat16(v1);
            __nv_bfloat16 l0 = __float2bfloat16(v0 - __bfloat162float(h0));
            __nv_bfloat16 l1 = __float2bfloat16(v1 - __bfloat162float(h1));
            unsigned ph = ((unsigned)__bfloat16_as_ushort(h1) << 16) | __bfloat16_as_ushort(h0);
            unsigned pl = ((unsigned)__bfloat16_as_ushort(l1) << 16) | __bfloat16_as_ushort(l0);
            *(unsigned*)(Ah + tok * 144 + d * 2) = ph;
            *(unsigned*)(Al + tok * 144 + d * 2) = pl;
        }
        sqp[tok * 4 + dblk] = s;
    }
    // ---- stage P: g_pbh/g_pbl [m][64] -> padded rows ----
    #pragma unroll
    for (int c = 0; c < 8; c++) {
        int e = t + 256 * c;            // < 2048
        int row = e >> 3, j = e & 7;
        *(uint4*)(Ph + row * 144 + j * 16) = ((const uint4*)g_pbh)[e];
        *(uint4*)(Pl + row * 144 + j * 16) = ((const uint4*)g_pbl)[e];
    }
    __syncthreads();
    if (t < 64) sq[t] = sqp[4*t] + sqp[4*t+1] + sqp[4*t+2] + sqp[4*t+3];

    const int w = t >> 5, lane = t & 31;
    const int g = lane >> 2, tq = lane & 3;
    const int tb = (w & 3) * 16;            // token base within block
    const int fb = (w >> 2) * 128;          // feature base (half)

    float c[16][4];
    #pragma unroll
    for (int nt = 0; nt < 16; nt++)
        #pragma unroll
        for (int j = 0; j < 4; j++) c[nt][j] = 0.0f;

    #pragma unroll
    for (int k = 0; k < 4; k++) {
        const int koff = k * 16;
        unsigned ah[4], al[4];
        ah[0] = *(const unsigned*)(Ah + (tb + g)     * 144 + (koff + 2*tq) * 2);
        ah[1] = *(const unsigned*)(Ah + (tb + g + 8) * 144 + (koff + 2*tq) * 2);
        ah[2] = *(const unsigned*)(Ah + (tb + g)     * 144 + (koff + 8 + 2*tq) * 2);
        ah[3] = *(const unsigned*)(Ah + (tb + g + 8) * 144 + (koff + 8 + 2*tq) * 2);
        al[0] = *(const unsigned*)(Al + (tb + g)     * 144 + (koff + 2*tq) * 2);
        al[1] = *(const unsigned*)(Al + (tb + g + 8) * 144 + (koff + 2*tq) * 2);
        al[2] = *(const unsigned*)(Al + (tb + g)     * 144 + (koff + 8 + 2*tq) * 2);
        al[3] = *(const unsigned*)(Al + (tb + g + 8) * 144 + (koff + 8 + 2*tq) * 2);
        #pragma unroll
        for (int nt = 0; nt < 16; nt++) {
            const char* prow_h = Ph + (fb + nt * 8 + g) * 144 + (koff + 2*tq) * 2;
            const char* prow_l = Pl + (fb + nt * 8 + g) * 144 + (koff + 2*tq) * 2;
            unsigned bh0 = *(const unsigned*)(prow_h);
            unsigned bh1 = *(const unsigned*)(prow_h + 16);
            unsigned bl0 = *(const unsigned*)(prow_l);
            unsigned bl1 = *(const unsigned*)(prow_l + 16);
            mma16816(c[nt], ah, bh0, bh1);
            mma16816(c[nt], ah, bl0, bl1);
            mma16816(c[nt], al, bh0, bh1);
        }
    }

    const int tl0 = tb + g, tl1 = tb + g + 8;
    const float dg0 = sq[tl0] * DIAGC;
    const float dg1 = sq[tl1] * DIAGC;

    if (!IS_QUERY) {
        // raw-u max -> per-head atomicMax; write u - diag
        float bm = -3.4e38f;
        float* kr0 = g_kbuf + ((size_t)head * Nn + n0 + tl0) * Mm + fb;
        float* kr1 = g_kbuf + ((size_t)head * Nn + n0 + tl1) * Mm + fb;
        #pragma unroll
        for (int nt = 0; nt < 16; nt++) {
            bm = fmaxf(bm, fmaxf(fmaxf(c[nt][0], c[nt][1]), fmaxf(c[nt][2], c[nt][3])));
            *(float2*)(kr0 + nt * 8 + 2*tq) = make_float2(c[nt][0] - dg0, c[nt][1] - dg0);
            *(float2*)(kr1 + nt * 8 + 2*tq) = make_float2(c[nt][2] - dg1, c[nt][3] - dg1);
        }
        #pragma unroll
        for (int o = 16; o; o >>= 1) bm = fmaxf(bm, __shfl_xor_sync(0xffffffffu, bm, o));
        if (lane == 0) atomicMax(g_kmax + head, fkey(bm));
    } else {
        // per-token max over features (two halves combined via smem)
        float m0 = -3.4e38f, m1 = -3.4e38f;
        #pragma unroll
        for (int nt = 0; nt < 16; nt++) {
            m0 = fmaxf(m0, fmaxf(c[nt][0], c[nt][1]));
            m1 = fmaxf(m1, fmaxf(c[nt][2], c[nt][3]));
        }
        m0 = fmaxf(m0, __shfl_xor_sync(0xffffffffu, m0, 1));
        m0 = fmaxf(m0, __shfl_xor_sync(0xffffffffu, m0, 2));
        m1 = fmaxf(m1, __shfl_xor_sync(0xffffffffu, m1, 1));
        m1 = fmaxf(m1, __shfl_xor_sync(0xffffffffu, m1, 2));
        if (tq == 0) {
            smax[(w >> 2) * 64 + tl0] = m0;
            smax[(w >> 2) * 64 + tl1] = m1;
        }
        __syncthreads();
        const float cc0 = -dg0 - fmaxf(smax[tl0], smax[64 + tl0]);
        const float cc1 = -dg1 - fmaxf(smax[tl1], smax[64 + tl1]);
        float* qr0 = g_qbuf + ((size_t)head * Nn + n0 + tl0) * Mm + fb;
        float* qr1 = g_qbuf + ((size_t)head * Nn + n0 + tl1) * Mm + fb;
        #pragma unroll
        for (int nt = 0; nt < 16; nt++) {
            *(float2*)(qr0 + nt * 8 + 2*tq) =
                make_float2(RATIO * fexp(c[nt][0] + cc0) + REPS,
                            RATIO * fexp(c[nt][1] + cc0) + REPS);
            *(float2*)(qr1 + nt * 8 + 2*tq) =
                make_float2(RATIO * fexp(c[nt][2] + cc1) + REPS,
                            RATIO * fexp(c[nt][3] + cc1) + REPS);
        }
    }
}

// ---------------- K2: k_phi + partial kv/knorm (scalar, proven R1) --------
__global__ void __launch_bounds__(256) k_kv_accum(const float* __restrict__ value)
{
    __shared__ float PHIs[32 * 264];
    __shared__ float Vs[32 * 68];

    const int t = threadIdx.x;
    const int head = blockIdx.y;
    const int slice = blockIdx.x;
    const float kmax = finv(g_kmax[head]);

    const int tm = (t >> 3) << 3;
    const int td = (t & 7) << 3;

    float acc[8][8];
    float nrm[8];
    #pragma unroll
    for (int i = 0; i < 8; i++) {
        nrm[i] = 0.0f;
        #pragma unroll
        for (int j = 0; j < 8; j++) acc[i][j] = 0.0f;
    }

    const float* vp = value + (size_t)head * Dd * Nn;
    const float* kb = g_kbuf + ((size_t)head * Nn + (size_t)slice * 512) * Mm;

    for (int c = 0; c < 16; c++) {
        const int n0 = slice * 512 + c * 32;
        __syncthreads();
        {
            const float4* src = (const float4*)(kb + (size_t)c * 32 * Mm);
            #pragma unroll
            for (int r = 0; r < 8; r++) {
                int e4 = t + 256 * r;
                int n = e4 >> 6, m4 = e4 & 63;
                float4 v = src[(size_t)n * 64 + m4];
                float4 p;
                p.x = RATIO * fexp(v.x - kmax) + REPS;
                p.y = RATIO * fexp(v.y - kmax) + REPS;
                p.z = RATIO * fexp(v.z - kmax) + REPS;
                p.w = RATIO * fexp(v.w - kmax) + REPS;
                *(float4*)(PHIs + n * 264 + m4 * 4) = p;
            }
        }
        {
            #pragma unroll
            for (int r = 0; r < 8; r++) {
                int idx = t + 256 * r;
                int n = idx & 31, d = idx >> 5;
                Vs[n * 68 + d] = vp[(size_t)d * Nn + n0 + n];
            }
        }
        __syncthreads();

        #pragma unroll 4
        for (int n = 0; n < 32; n++) {
            float4 a0 = *(const float4*)(PHIs + n * 264 + tm);
            float4 a1 = *(const float4*)(PHIs + n * 264 + tm + 4);
            float4 b0 = *(const float4*)(Vs + n * 68 + td);
            float4 b1 = *(const float4*)(Vs + n * 68 + td + 4);
            float av[8] = {a0.x,a0.y,a0.z,a0.w,a1.x,a1.y,a1.z,a1.w};
            float bv[8] = {b0.x,b0.y,b0.z,b0.w,b1.x,b1.y,b1.z,b1.w};
            if ((t & 7) == 0) {
                #pragma unroll
                for (int i = 0; i < 8; i++) nrm[i] += av[i];
            }
            #pragma unroll
            for (int j = 0; j < 8; j++)
                #pragma unroll
                for (int i = 0; i < 8; i++) acc[i][j] = fmaf(av[i], bv[j], acc[i][j]);
        }
    }

    float* dst = g_kvpart + (size_t)(head * 16 + slice) * 17408;
    #pragma unroll
    for (int i = 0; i < 8; i++) {
        *(float4*)(dst + (tm + i) * 68 + td) =
            make_float4(acc[i][0], acc[i][1], acc[i][2], acc[i][3]);
        *(float4*)(dst + (tm + i) * 68 + td + 4) =
            make_float4(acc[i][4], acc[i][5], acc[i][6], acc[i][7]);
        if ((t & 7) == 0) dst[(tm + i) * 68 + 64] = nrm[i];
    }
}

// ---------------- K3: reduce partials -> g_kvaug ----------------
__global__ void k_reduce()
{
    int idx = blockIdx.x * 256 + threadIdx.x;
    int h = idx / 17408;
    int j = idx - h * 17408;
    float s = 0.0f;
    if (j % 68 < 65) {
        #pragma unroll
        for (int sl = 0; sl < 16; sl++)
            s += g_kvpart[(size_t)(h * 16 + sl) * 17408 + j];
    }
    g_kvaug[idx] = s;
}

// ---------------- K4: output GEMM (scalar, phi_q precomputed) --------------
__global__ void __launch_bounds__(256) k_out(float* __restrict__ out)
{
    extern __shared__ float sm[];
    float* PHIs = sm;            // [256 m][68] (col = token)
    float* KVs  = sm + 17408;    // [256 m][68]

    const int t = threadIdx.x;
    const int head = blockIdx.y;
    const int n0 = blockIdx.x * 64;

    {   // stage PHIs from g_qbuf [token][m]
        const float* qb = g_qbuf + ((size_t)head * Nn + n0) * Mm;
        #pragma unroll
        for (int r = 0; r < 16; r++) {
            int e = t + 256 * r;        // < 4096
            int n = e & 63, m4 = e >> 6;
            float4 v = *(const float4*)(qb + (size_t)n * Mm + m4 * 4);
            PHIs[(m4 * 4 + 0) * 68 + n] = v.x;
            PHIs[(m4 * 4 + 1) * 68 + n] = v.y;
            PHIs[(m4 * 4 + 2) * 68 + n] = v.z;
            PHIs[(m4 * 4 + 3) * 68 + n] = v.w;
        }
    }
    {   // stage KVs (linear copy)
        const float4* s4 = (const float4*)(g_kvaug + (size_t)head * 17408);
        float4* d4 = (float4*)KVs;
        #pragma unroll
        for (int r = 0; r < 17; r++) d4[t + 256 * r] = s4[t + 256 * r];
    }
    __syncthreads();

    const int qn = (t & 15) << 2;
    const int qd = (t >> 4) << 2;
    float oa[4][4];
    float on[4];
    #pragma unroll
    for (int j = 0; j < 4; j++) {
        on[j] = 0.0f;
        #pragma unroll
        for (int d2 = 0; d2 < 4; d2++) oa[j][d2] = 0.0f;
    }

    #pragma unroll 4
    for (int m = 0; m < 256; m++) {
        float4 p  = *(const float4*)(PHIs + m * 68 + qn);
        float4 kv = *(const float4*)(KVs + m * 68 + qd);
        float  kn = KVs[m * 68 + 64];
        float pv[4]  = {p.x, p.y, p.z, p.w};
        float kvv[4] = {kv.x, kv.y, kv.z, kv.w};
        #pragma unroll
        for (int j = 0; j < 4; j++) {
            on[j] = fmaf(pv[j], kn, on[j]);
            #pragma unroll
            for (int d2 = 0; d2 < 4; d2++)
                oa[j][d2] = fmaf(pv[j], kvv[d2], oa[j][d2]);
        }
    }

    float rn[4];
    #pragma unroll
    for (int j = 0; j < 4; j++) rn[j] = 1.0f / on[j];

    float* op = out + (size_t)head * Dd * Nn + n0 + qn;
    #pragma unroll
    for (int d2 = 0; d2 < 4; d2++) {
        *(float4*)(op + (size_t)(qd + d2) * Nn) =
            make_float4(oa[0][d2] * rn[0], oa[1][d2] * rn[1],
                        oa[2][d2] * rn[2], oa[3][d2] * rn[3]);
    }
}

// ---------------- launch ----------------
extern "C" void kernel_launch(void* const* d_in, const int* in_sizes, int n_in,
                              void* d_out, int out_size)
{
    const float* query = (const float*)d_in[0];
    const float* key   = (const float*)d_in[1];
    const float* value = (const float*)d_in[2];
    const float* proj  = (const float*)d_in[3];
    float* out = (float*)d_out;

    cudaFuncSetAttribute(k_proj_mma<false>, cudaFuncAttributeMaxDynamicSharedMemorySize, PROJ_SMEM);
    cudaFuncSetAttribute(k_proj_mma<true>,  cudaFuncAttributeMaxDynamicSharedMemorySize, PROJ_SMEM);
    cudaFuncSetAttribute(k_out, cudaFuncAttributeMaxDynamicSharedMemorySize, 139264);

    k_init<<<64, 256>>>(proj);
    k_proj_mma<false><<<dim3(128, 32), 256, PROJ_SMEM>>>(key);
    k_proj_mma<true><<<dim3(128, 32), 256, PROJ_SMEM>>>(query);
    k_kv_accum<<<dim3(16, 32), 256>>>(value);
    k_reduce<<<2176, 256>>>();
    k_out<<<dim3(128, 32), 256, 139264>>>(out);
}

// round 7
// speedup vs baseline: 1.8382x; 1.0823x over previous
#include <cuda_runtime.h>
#include <cuda_bf16.h>
#include <math.h>

#define Dd 64
#define Nn 8192
#define Mm 256
#define NH 32
#define DN     0.3535533905932738f   /* 64^-0.25 */
#define RATIO  0.0625f               /* 256^-0.5 */
#define REPS   6.25e-8f              /* RATIO * 1e-6 */
#define DIAGC  0.0625f               /* DN^2 * 0.5 */

// ---------------- scratch (device globals; no allocation) ----------------
__device__ float    g_kbuf[(size_t)NH * Mm * Nn];          // [h][m][n] : u - diag (keys)
__device__ __nv_bfloat16 g_qh[(size_t)NH * Nn * Mm];       // phi_q hi, [h][tok][m]
__device__ __nv_bfloat16 g_ql[(size_t)NH * Nn * Mm];       // phi_q lo
__device__ unsigned g_kmax[NH];                            // per-head max(raw u), ordered key
__device__ float    g_kvpart[(size_t)NH * 16 * 80 * 256];  // [h*16+sl][d][m]
__device__ __nv_bfloat16 g_kvth[(size_t)NH * 80 * 256];    // kv^T hi, [h][d][m] (d=64 -> knorm)
__device__ __nv_bfloat16 g_kvtl[(size_t)NH * 80 * 256];    // kv^T lo
__device__ __align__(16) __nv_bfloat16 g_pbh[256 * 64];    // proj*DN hi, [m][d]
__device__ __align__(16) __nv_bfloat16 g_pbl[256 * 64];    // proj*DN lo

// order-preserving float<->uint key
static __device__ __forceinline__ unsigned fkey(float f) {
    unsigned b = __float_as_uint(f);
    return (b & 0x80000000u) ? ~b : (b | 0x80000000u);
}
static __device__ __forceinline__ float finv(unsigned k) {
    return __uint_as_float((k & 0x80000000u) ? (k & 0x7fffffffu) : ~k);
}

// branch-free exp on FMA/ALU pipes. Valid for x <= 0, ~2.4e-6 rel err.
static __device__ __forceinline__ float fexp(float x) {
    float t = x * 1.4426950408889634f;
    t = fmaxf(t, -125.0f);
    float r  = t + 12582912.0f;
    float fi = r - 12582912.0f;
    float f  = t - fi;
    float p = 1.3333558e-3f;
    p = fmaf(p, f, 9.6181291e-3f);
    p = fmaf(p, f, 5.5504109e-2f);
    p = fmaf(p, f, 2.4022651e-1f);
    p = fmaf(p, f, 6.9314718e-1f);
    p = fmaf(p, f, 1.0f);
    int ib = __float_as_int(r) - 0x4B400000;
    float s = __int_as_float((ib + 127) << 23);
    return p * s;
}

// HMMA m16n8k16 bf16 -> fp32 accum
static __device__ __forceinline__ void mma16816(float c[4], const unsigned a[4],
                                                unsigned b0, unsigned b1) {
    asm volatile(
        "mma.sync.aligned.m16n8k16.row.col.f32.bf16.bf16.f32 "
        "{%0,%1,%2,%3}, {%4,%5,%6,%7}, {%8,%9}, {%0,%1,%2,%3};"
        : "+f"(c[0]), "+f"(c[1]), "+f"(c[2]), "+f"(c[3])
        : "r"(a[0]), "r"(a[1]), "r"(a[2]), "r"(a[3]), "r"(b0), "r"(b1));
}

// bf16 hi/lo split, packing pairs (v0,v1) -> (hi-pair, lo-pair)
static __device__ __forceinline__ void split2(float v0, float v1, unsigned& ph, unsigned& pl) {
    __nv_bfloat16 h0 = __float2bfloat16(v0);
    __nv_bfloat16 h1 = __float2bfloat16(v1);
    __nv_bfloat16 l0 = __float2bfloat16(v0 - __bfloat162float(h0));
    __nv_bfloat16 l1 = __float2bfloat16(v1 - __bfloat162float(h1));
    ph = ((unsigned)__bfloat16_as_ushort(h1) << 16) | __bfloat16_as_ushort(h0);
    pl = ((unsigned)__bfloat16_as_ushort(l1) << 16) | __bfloat16_as_ushort(l0);
}

// ---------------- K0: bf16-split scaled proj + reset kmax ----------------
__global__ void k_init(const float* __restrict__ proj)
{
    int idx = blockIdx.x * 256 + threadIdx.x;   // 64 blocks x 256
    if (idx < 256 * 64) {
        float v = proj[idx] * DN;               // [m][d] layout preserved
        __nv_bfloat16 h = __float2bfloat16(v);
        g_pbh[idx] = h;
        g_pbl[idx] = __float2bfloat16(v - __bfloat162float(h));
    }
    if (idx < NH) g_kmax[idx] = 0u;
}

// ---------------- K_proj (HMMA): u = x . P^T per 64-token block ------------
// grid (128, 32), block 256 (8 warps). Warp tile: 16 tokens x 128 features.
#define OFF_AH   0
#define OFF_AL   9216
#define OFF_PH   18432
#define OFF_PL   55296
#define OFF_SQP  92160
#define OFF_SQ   93184
#define OFF_SMAX 93440
#define PROJ_SMEM 94208

template <bool IS_QUERY>
__global__ void __launch_bounds__(256, 2) k_proj_mma(const float* __restrict__ x)
{
    extern __shared__ char smem[];
    char* Ah = smem + OFF_AH;       // [64 tok][72 bf16]
    char* Al = smem + OFF_AL;
    char* Ph = smem + OFF_PH;       // [256 feat][72 bf16]
    char* Pl = smem + OFF_PL;
    float* sqp  = (float*)(smem + OFF_SQP);   // [64][4]
    float* sq   = (float*)(smem + OFF_SQ);    // [64]
    float* smax = (float*)(smem + OFF_SMAX);  // [2][64]

    const int t = threadIdx.x;
    const int head = blockIdx.y;
    const int n0 = blockIdx.x * 64;

    // ---- stage A: x[d][tok] -> Ah/Al[tok][d] bf16 pairs + partial sumsq ----
    {
        const int tok = t & 63, dblk = t >> 6;
        const float* xp = x + (size_t)head * Dd * Nn + n0 + tok;
        float s = 0.0f;
        #pragma unroll
        for (int i = 0; i < 8; i++) {
            int d = dblk * 16 + 2 * i;
            float v0 = xp[(size_t)d * Nn];
            float v1 = xp[(size_t)(d + 1) * Nn];
            s = fmaf(v0, v0, fmaf(v1, v1, s));
            unsigned ph, pl;
            split2(v0, v1, ph, pl);
            *(unsigned*)(Ah + tok * 144 + d * 2) = ph;
            *(unsigned*)(Al + tok * 144 + d * 2) = pl;
        }
        sqp[tok * 4 + dblk] = s;
    }
    // ---- stage P ----
    #pragma unroll
    for (int cc = 0; cc < 8; cc++) {
        int e = t + 256 * cc;           // < 2048
        int row = e >> 3, j = e & 7;
        *(uint4*)(Ph + row * 144 + j * 16) = ((const uint4*)g_pbh)[e];
        *(uint4*)(Pl + row * 144 + j * 16) = ((const uint4*)g_pbl)[e];
    }
    __syncthreads();
    if (t < 64) sq[t] = sqp[4*t] + sqp[4*t+1] + sqp[4*t+2] + sqp[4*t+3];

    const int w = t >> 5, lane = t & 31;
    const int g = lane >> 2, tq = lane & 3;
    const int tb = (w & 3) * 16;            // token base
    const int fb = (w >> 2) * 128;          // feature base

    float c[16][4];
    #pragma unroll
    for (int nt = 0; nt < 16; nt++)
        #pragma unroll
        for (int j = 0; j < 4; j++) c[nt][j] = 0.0f;

    #pragma unroll
    for (int k = 0; k < 4; k++) {
        const int koff = k * 16;
        unsigned ah[4], al[4];
        ah[0] = *(const unsigned*)(Ah + (tb + g)     * 144 + (koff + 2*tq) * 2);
        ah[1] = *(const unsigned*)(Ah + (tb + g + 8) * 144 + (koff + 2*tq) * 2);
        ah[2] = *(const unsigned*)(Ah + (tb + g)     * 144 + (koff + 8 + 2*tq) * 2);
        ah[3] = *(const unsigned*)(Ah + (tb + g + 8) * 144 + (koff + 8 + 2*tq) * 2);
        al[0] = *(const unsigned*)(Al + (tb + g)     * 144 + (koff + 2*tq) * 2);
        al[1] = *(const unsigned*)(Al + (tb + g + 8) * 144 + (koff + 2*tq) * 2);
        al[2] = *(const unsigned*)(Al + (tb + g)     * 144 + (koff + 8 + 2*tq) * 2);
        al[3] = *(const unsigned*)(Al + (tb + g + 8) * 144 + (koff + 8 + 2*tq) * 2);
        #pragma unroll
        for (int nt = 0; nt < 16; nt++) {
            const char* prow_h = Ph + (fb + nt * 8 + g) * 144 + (koff + 2*tq) * 2;
            const char* prow_l = Pl + (fb + nt * 8 + g) * 144 + (koff + 2*tq) * 2;
            unsigned bh0 = *(const unsigned*)(prow_h);
            unsigned bh1 = *(const unsigned*)(prow_h + 16);
            unsigned bl0 = *(const unsigned*)(prow_l);
            unsigned bl1 = *(const unsigned*)(prow_l + 16);
            mma16816(c[nt], ah, bh0, bh1);
            mma16816(c[nt], ah, bl0, bl1);
            mma16816(c[nt], al, bh0, bh1);
        }
    }

    const int tl0 = tb + g, tl1 = tb + g + 8;
    const float dg0 = sq[tl0] * DIAGC;
    const float dg1 = sq[tl1] * DIAGC;

    if (!IS_QUERY) {
        // raw-u max -> per-head atomicMax
        float bm = -3.4e38f;
        #pragma unroll
        for (int nt = 0; nt < 16; nt++)
            bm = fmaxf(bm, fmaxf(fmaxf(c[nt][0], c[nt][1]), fmaxf(c[nt][2], c[nt][3])));
        #pragma unroll
        for (int o = 16; o; o >>= 1) bm = fmaxf(bm, __shfl_xor_sync(0xffffffffu, bm, o));
        if (lane == 0) atomicMax(g_kmax + head, fkey(bm));

        // transpose (u - diag) into smem [256 m][68 tok], then coalesced write [m][n]
        __syncthreads();                // all MMA smem reads done
        float* Tr = (float*)(smem + OFF_PH);    // [256][68] f32 = 69632 B
        #pragma unroll
        for (int nt = 0; nt < 16; nt++) {
            int m = fb + nt * 8 + 2 * tq;
            Tr[m * 68 + tl0]       = c[nt][0] - dg0;
            Tr[(m + 1) * 68 + tl0] = c[nt][1] - dg0;
            Tr[m * 68 + tl1]       = c[nt][2] - dg1;
            Tr[(m + 1) * 68 + tl1] = c[nt][3] - dg1;
        }
        __syncthreads();
        const int q = t & 3;
        #pragma unroll
        for (int p = 0; p < 4; p++) {
            int m = (t >> 2) + p * 64;
            float* drow = g_kbuf + ((size_t)(head * Mm + m)) * Nn + n0 + q * 16;
            #pragma unroll
            for (int i = 0; i < 4; i++)
                *(float4*)(drow + 4 * i) = *(const float4*)(Tr + m * 68 + q * 16 + 4 * i);
        }
    } else {
        // per-token max over features (two halves combined via smem)
        float m0 = -3.4e38f, m1 = -3.4e38f;
        #pragma unroll
        for (int nt = 0; nt < 16; nt++) {
            m0 = fmaxf(m0, fmaxf(c[nt][0], c[nt][1]));
            m1 = fmaxf(m1, fmaxf(c[nt][2], c[nt][3]));
        }
        m0 = fmaxf(m0, __shfl_xor_sync(0xffffffffu, m0, 1));
        m0 = fmaxf(m0, __shfl_xor_sync(0xffffffffu, m0, 2));
        m1 = fmaxf(m1, __shfl_xor_sync(0xffffffffu, m1, 1));
        m1 = fmaxf(m1, __shfl_xor_sync(0xffffffffu, m1, 2));
        if (tq == 0) {
            smax[(w >> 2) * 64 + tl0] = m0;
            smax[(w >> 2) * 64 + tl1] = m1;
        }
        __syncthreads();                // MMA reads done; smax ready
        const float cc0 = -dg0 - fmaxf(smax[tl0], smax[64 + tl0]);
        const float cc1 = -dg1 - fmaxf(smax[tl1], smax[64 + tl1]);
        unsigned* Trh = (unsigned*)(smem + OFF_PH);   // [64 tok][132 u32] (264 bf16)
        unsigned* Trl = Trh + 64 * 132;
        #pragma unroll
        for (int nt = 0; nt < 16; nt++) {
            int m = fb + nt * 8 + 2 * tq;
            float p0 = RATIO * fexp(c[nt][0] + cc0) + REPS;
            float p1 = RATIO * fexp(c[nt][1] + cc0) + REPS;
            float p2 = RATIO * fexp(c[nt][2] + cc1) + REPS;
            float p3 = RATIO * fexp(c[nt][3] + cc1) + REPS;
            unsigned ph, pl;
            split2(p0, p1, ph, pl);
            Trh[tl0 * 132 + (m >> 1)] = ph;
            Trl[tl0 * 132 + (m >> 1)] = pl;
            split2(p2, p3, ph, pl);
            Trh[tl1 * 132 + (m >> 1)] = ph;
            Trl[tl1 * 132 + (m >> 1)] = pl;
        }
        __syncthreads();
        const int tok = t >> 2, q = t & 3;
        uint4* dh = (uint4*)(g_qh + ((size_t)head * Nn + n0 + tok) * Mm);
        uint4* dl = (uint4*)(g_ql + ((size_t)head * Nn + n0 + tok) * Mm);
        const uint4* sh = (const uint4*)(Trh + tok * 132 + q * 32);
        const uint4* sl = (const uint4*)(Trl + tok * 132 + q * 32);
        #pragma unroll
        for (int j = 0; j < 8; j++) {
            dh[q * 8 + j] = sh[j];
            dl[q * 8 + j] = sl[j];
        }
    }
}

// ---------------- K2 (HMMA): kv partials = phi_k . V^T (with knorm col) ----
// grid (16 slices, 32 heads), block 256 (8 warps). n-slice = 512, chunk = 64.
// C[m=256][d=80], warp tile 64 m x 40 d. V padded: row 64 = ones, 65..79 = 0.
#define KV_AH  0
#define KV_AL  36864
#define KV_VH  73728
#define KV_VL  85248
#define KV_SMEM 96768

__global__ void __launch_bounds__(256, 1) k_kv_mma(const float* __restrict__ value)
{
    extern __shared__ char smem[];
    char* Ah = smem + KV_AH;   // [256 m][72 bf16] (144 B rows)
    char* Al = smem + KV_AL;
    char* Vh = smem + KV_VH;   // [80 d][72 bf16]
    char* Vl = smem + KV_VL;

    const int t = threadIdx.x;
    const int head = blockIdx.y;
    const int slice = blockIdx.x;
    const float kmax = finv(g_kmax[head]);

    const int w = t >> 5, lane = t & 31;
    const int g = lane >> 2, tq = lane & 3;
    const int mg = (w & 3) * 64;
    const int dg = (w >> 2) * 40;

    // V pad rows 64..79: row 64 = 1.0 (knorm), rest 0
    for (int e = t; e < 576; e += 256) {          // 16 rows x 36 u32
        int row = 64 + e / 36, col = e % 36;
        ((unsigned*)(Vh + row * 144))[col] = (row == 64) ? 0x3F803F80u : 0u;
        ((unsigned*)(Vl + row * 144))[col] = 0u;
    }

    float c[4][5][4];
    #pragma unroll
    for (int mt = 0; mt < 4; mt++)
        #pragma unroll
        for (int dt = 0; dt < 5; dt++)
            #pragma unroll
            for (int j = 0; j < 4; j++) c[mt][dt][j] = 0.0f;

    const float* vp = value + (size_t)head * Dd * Nn;
    const int q = t & 3;

    for (int ch = 0; ch < 8; ch++) {
        const int n0 = slice * 512 + ch * 64;
        __syncthreads();   // previous MMA reads complete

        // stage A: phi_k bf16 split, [m][n] rows
        #pragma unroll
        for (int p = 0; p < 4; p++) {
            int m = (t >> 2) + p * 64;
            const float* src = g_kbuf + ((size_t)(head * Mm + m)) * Nn + n0 + q * 16;
            unsigned* rowh = (unsigned*)(Ah + m * 144 + q * 32);
            unsigned* rowl = (unsigned*)(Al + m * 144 + q * 32);
            #pragma unroll
            for (int i = 0; i < 4; i++) {
                float4 v = *(const float4*)(src + 4 * i);
                float p0 = RATIO * fexp(v.x - kmax) + REPS;
                float p1 = RATIO * fexp(v.y - kmax) + REPS;
                float p2 = RATIO * fexp(v.z - kmax) + REPS;
                float p3 = RATIO * fexp(v.w - kmax) + REPS;
                unsigned ph, pl;
                split2(p0, p1, ph, pl);
                rowh[2 * i] = ph;  rowl[2 * i] = pl;
                split2(p2, p3, ph, pl);
                rowh[2 * i + 1] = ph;  rowl[2 * i + 1] = pl;
            }
        }
        // stage V: [d][n] rows (real d = 64)
        {
            int d = t >> 2;
            const float* src = vp + (size_t)d * Nn + n0 + q * 16;
            unsigned* rowh = (unsigned*)(Vh + d * 144 + q * 32);
            unsigned* rowl = (unsigned*)(Vl + d * 144 + q * 32);
            #pragma unroll
            for (int i = 0; i < 4; i++) {
                float4 v = *(const float4*)(src + 4 * i);
                unsigned ph, pl;
                split2(v.x, v.y, ph, pl);
                rowh[2 * i] = ph;  rowl[2 * i] = pl;
                split2(v.z, v.w, ph, pl);
                rowh[2 * i + 1] = ph;  rowl[2 * i + 1] = pl;
            }
        }
        __syncthreads();

        #pragma unroll
        for (int k = 0; k < 4; k++) {
            const int koff = k * 16;
            unsigned ah[4][4], al[4][4];
            #pragma unroll
            for (int mt = 0; mt < 4; mt++) {
                int r0 = mg + mt * 16 + g, r1 = r0 + 8;
                ah[mt][0] = *(const unsigned*)(Ah + r0 * 144 + (koff + 2*tq) * 2);
                ah[mt][1] = *(const unsigned*)(Ah + r1 * 144 + (koff + 2*tq) * 2);
                ah[mt][2] = *(const unsigned*)(Ah + r0 * 144 + (koff + 8 + 2*tq) * 2);
                ah[mt][3] = *(const unsigned*)(Ah + r1 * 144 + (koff + 8 + 2*tq) * 2);
                al[mt][0] = *(const unsigned*)(Al + r0 * 144 + (koff + 2*tq) * 2);
                al[mt][1] = *(const unsigned*)(Al + r1 * 144 + (koff + 2*tq) * 2);
                al[mt][2] = *(const unsigned*)(Al + r0 * 144 + (koff + 8 + 2*tq) * 2);
                al[mt][3] = *(const unsigned*)(Al + r1 * 144 + (koff + 8 + 2*tq) * 2);
            }
            #pragma unroll
            for (int dt = 0; dt < 5; dt++) {
                const char* rh = Vh + (dg + dt * 8 + g) * 144 + (koff + 2*tq) * 2;
                const char* rl = Vl + (dg + dt * 8 + g) * 144 + (koff + 2*tq) * 2;
                unsigned bh0 = *(const unsigned*)(rh);
                unsigned bh1 = *(const unsigned*)(rh + 16);
                unsigned bl0 = *(const unsigned*)(rl);
                unsigned bl1 = *(const unsigned*)(rl + 16);
                #pragma unroll
                for (int mt = 0; mt < 4; mt++) {
                    mma16816(c[mt][dt], ah[mt], bh0, bh1);
                    mma16816(c[mt][dt], ah[mt], bl0, bl1);
                    mma16816(c[mt][dt], al[mt], bh0, bh1);
                }
            }
        }
    }

    // write partials [d][m]
    float* dst = g_kvpart + (size_t)(head * 16 + slice) * 20480;
    #pragma unroll
    for (int mt = 0; mt < 4; mt++) {
        int m0 = mg + mt * 16 + g, m1 = m0 + 8;
        #pragma unroll
        for (int dt = 0; dt < 5; dt++) {
            int d0 = dg + dt * 8 + 2 * tq;
            dst[d0 * 256 + m0]       = c[mt][dt][0];
            dst[(d0 + 1) * 256 + m0] = c[mt][dt][1];
            dst[d0 * 256 + m1]       = c[mt][dt][2];
            dst[(d0 + 1) * 256 + m1] = c[mt][dt][3];
        }
    }
}

// ---------------- K3: reduce partials -> bf16-split kv^T ----------------
__global__ void k_reduce()
{
    int idx = blockIdx.x * 256 + threadIdx.x;   // < 32*80*256 = 655360
    int h = idx / 20480;
    int rem = idx - h * 20480;
    float s = 0.0f;
    #pragma unroll
    for (int sl = 0; sl < 16; sl++)
        s += g_kvpart[(size_t)(h * 16 + sl) * 20480 + rem];
    __nv_bfloat16 hi = __float2bfloat16(s);
    g_kvth[idx] = hi;
    g_kvtl[idx] = __float2bfloat16(s - __bfloat162float(hi));
}

// ---------------- K4 (HMMA): out = phi_q . kv, divide by norm col ----------
// grid (128, 32), block 256 (8 warps). 64 tokens x 80 d. Warp: 16 tok x 40 d.
#define QO_QH 0
#define QO_QL 33792
#define QO_KH 67584
#define QO_KL 109824
#define QO_SN 152064
#define QO_SMEM 152320

__global__ void __launch_bounds__(256, 1) k_out_mma(float* __restrict__ out)
{
    extern __shared__ char smem[];
    char* Qh = smem + QO_QH;   // [64 tok][264 bf16] (528 B rows)
    char* Ql = smem + QO_QL;
    char* Kh = smem + QO_KH;   // [80 d][264 bf16]
    char* Kl = smem + QO_KL;
    float* sn = (float*)(smem + QO_SN);   // [64]

    const int t = threadIdx.x;
    const int head = blockIdx.y;
    const int n0 = blockIdx.x * 64;

    // stage phi_q (hi/lo)
    {
        int tok = t >> 2, q = t & 3;
        const uint4* sh = (const uint4*)(g_qh + ((size_t)head * Nn + n0 + tok) * Mm + q * 64);
        const uint4* sl = (const uint4*)(g_ql + ((size_t)head * Nn + n0 + tok) * Mm + q * 64);
        uint4* dh = (uint4*)(Qh + tok * 528 + q * 128);
        uint4* dl = (uint4*)(Ql + tok * 528 + q * 128);
        #pragma unroll
        for (int j = 0; j < 8; j++) { dh[j] = sh[j]; dl[j] = sl[j]; }
    }
    // stage kv^T (hi/lo), 80 rows
    #pragma unroll
    for (int r = 0; r < 2; r++) {
        int e = t + 256 * r;
        if (e < 320) {
            int row = e >> 2, q = e & 3;
            const uint4* sh = (const uint4*)(g_kvth + ((size_t)head * 80 + row) * 256 + q * 64);
            const uint4* sl = (const uint4*)(g_kvtl + ((size_t)head * 80 + row) * 256 + q * 64);
            uint4* dh = (uint4*)(Kh + row * 528 + q * 128);
            uint4* dl = (uint4*)(Kl + row * 528 + q * 128);
            #pragma unroll
            for (int j = 0; j < 8; j++) { dh[j] = sh[j]; dl[j] = sl[j]; }
        }
    }
    __syncthreads();

    const int w = t >> 5, lane = t & 31;
    const int g = lane >> 2, tq = lane & 3;
    const int tg = (w & 3) * 16;
    const int dg = (w >> 2) * 40;

    float c[5][4];
    #pragma unroll
    for (int dt = 0; dt < 5; dt++)
        #pragma unroll
        for (int j = 0; j < 4; j++) c[dt][j] = 0.0f;

    #pragma unroll
    for (int kc = 0; kc < 16; kc++) {
        const int koff = kc * 16;
        unsigned ah[4], al[4];
        ah[0] = *(const unsigned*)(Qh + (tg + g)     * 528 + (koff + 2*tq) * 2);
        ah[1] = *(const unsigned*)(Qh + (tg + g + 8) * 528 + (koff + 2*tq) * 2);
        ah[2] = *(const unsigned*)(Qh + (tg + g)     * 528 + (koff + 8 + 2*tq) * 2);
        ah[3] = *(const unsigned*)(Qh + (tg + g + 8) * 528 + (koff + 8 + 2*tq) * 2);
        al[0] = *(const unsigned*)(Ql + (tg + g)     * 528 + (koff + 2*tq) * 2);
        al[1] = *(const unsigned*)(Ql + (tg + g + 8) * 528 + (koff + 2*tq) * 2);
        al[2] = *(const unsigned*)(Ql + (tg + g)     * 528 + (koff + 8 + 2*tq) * 2);
        al[3] = *(const unsigned*)(Ql + (tg + g + 8) * 528 + (koff + 8 + 2*tq) * 2);
        #pragma unroll
        for (int dt = 0; dt < 5; dt++) {
            const char* rh = Kh + (dg + dt * 8 + g) * 528 + (koff + 2*tq) * 2;
            const char* rl = Kl + (dg + dt * 8 + g) * 528 + (koff + 2*tq) * 2;
            unsigned bh0 = *(const unsigned*)(rh);
            unsigned bh1 = *(const unsigned*)(rh + 16);
            unsigned bl0 = *(const unsigned*)(rl);
            unsigned bl1 = *(const unsigned*)(rl + 16);
            mma16816(c[dt], ah, bh0, bh1);
            mma16816(c[dt], ah, bl0, bl1);
            mma16816(c[dt], al, bh0, bh1);
        }
    }

    // norm column (d = 64) held by warps w>=4, dt=3, tq==0
    if (w >= 4 && tq == 0) {
        sn[tg + g]     = c[3][0];
        sn[tg + g + 8] = c[3][2];
    }
    __syncthreads();
    const float rn0 = 1.0f / sn[tg + g];
    const float rn1 = 1.0f / sn[tg + g + 8];

    float* op = out + (size_t)head * Dd * Nn + n0;
    #pragma unroll
    for (int dt = 0; dt < 5; dt++) {
        int d0 = dg + dt * 8 + 2 * tq;
        if (d0 < 64) {
            op[(size_t)d0 * Nn + tg + g]           = c[dt][0] * rn0;
            op[(size_t)(d0 + 1) * Nn + tg + g]     = c[dt][1] * rn0;
            op[(size_t)d0 * Nn + tg + g + 8]       = c[dt][2] * rn1;
            op[(size_t)(d0 + 1) * Nn + tg + g + 8] = c[dt][3] * rn1;
        }
    }
}

// ---------------- launch ----------------
extern "C" void kernel_launch(void* const* d_in, const int* in_sizes, int n_in,
                              void* d_out, int out_size)
{
    const float* query = (const float*)d_in[0];
    const float* key   = (const float*)d_in[1];
    const float* value = (const float*)d_in[2];
    const float* proj  = (const float*)d_in[3];
    float* out = (float*)d_out;

    cudaFuncSetAttribute(k_proj_mma<false>, cudaFuncAttributeMaxDynamicSharedMemorySize, PROJ_SMEM);
    cudaFuncSetAttribute(k_proj_mma<true>,  cudaFuncAttributeMaxDynamicSharedMemorySize, PROJ_SMEM);
    cudaFuncSetAttribute(k_kv_mma,  cudaFuncAttributeMaxDynamicSharedMemorySize, KV_SMEM);
    cudaFuncSetAttribute(k_out_mma, cudaFuncAttributeMaxDynamicSharedMemorySize, QO_SMEM);

    k_init<<<64, 256>>>(proj);
    k_proj_mma<false><<<dim3(128, 32), 256, PROJ_SMEM>>>(key);
    k_proj_mma<true><<<dim3(128, 32), 256, PROJ_SMEM>>>(query);
    k_kv_mma<<<dim3(16, 32), 256, KV_SMEM>>>(value);
    k_reduce<<<2560, 256>>>();
    k_out_mma<<<dim3(128, 32), 256, QO_SMEM>>>(out);
}